// round 4
// baseline (speedup 1.0000x reference)
#include <cuda_runtime.h>
#include <math.h>

// ---------------------------------------------------------------------------
// GATNet: 4x GATConv + pool + MLP head.
// CSR-by-dst, single-pass softmax (no max subtraction), and FUSED
// aggregation+next-layer-transform kernels with ping-pong buffers.
// ---------------------------------------------------------------------------

#define NNODES 20000
#define E0     320000
#define ETOT   (E0 + NNODES)
#define NG     8
#define SCAN_T 1024
#define SCAN_CHUNK ((NNODES + SCAN_T - 1) / SCAN_T)   // 20

// Ping-pong feature/logit buffers (layers 1-3 are 64-wide)
__device__ __align__(16) float g_ft0[NNODES * 64];
__device__ __align__(16) float g_ft1[NNODES * 64];
__device__ __align__(16) float g_as0[NNODES * 8];
__device__ __align__(16) float g_ad0[NNODES * 8];
__device__ __align__(16) float g_as1[NNODES * 8];
__device__ __align__(16) float g_ad1[NNODES * 8];
// Layer-4 operands
__device__ __align__(16) float g_ft4[NNODES * 256];
__device__ __align__(16) float g_as4[NNODES * 4];
__device__ __align__(16) float g_ad4[NNODES * 4];
// Final node features
__device__ __align__(16) float g_featA[NNODES * 64];
__device__ float g_fp[NG * 64];
// CSR by destination
__device__ int g_cnt[NNODES];
__device__ int g_rowstart[NNODES + 1];
__device__ int g_cursor[NNODES];
__device__ int g_col[ETOT];

__device__ __forceinline__ float leaky02(float v) { return fmaxf(v, 0.2f * v); }
__device__ __forceinline__ float eluf(float v)    { return v > 0.f ? v : (__expf(v) - 1.f); }

// ---------------------------------------------------------------------------
// CSR build
// ---------------------------------------------------------------------------
__global__ void k_zero_cnt() {
    int t = blockIdx.x * blockDim.x + threadIdx.x;
    if (t < NNODES) g_cnt[t] = 0;
}
__global__ void k_count(const int* __restrict__ ei) {
    int e = blockIdx.x * blockDim.x + threadIdx.x;
    if (e >= ETOT) return;
    int d = (e < E0) ? ei[E0 + e] : (e - E0);
    atomicAdd(&g_cnt[d], 1);
}
__global__ void k_scan() {
    __shared__ int sp[SCAN_T];
    int t = threadIdx.x;
    int b0 = t * SCAN_CHUNK;
    int b1 = min(b0 + SCAN_CHUNK, NNODES);
    int sum = 0;
    for (int i = b0; i < b1; i++) sum += g_cnt[i];
    sp[t] = sum;
    __syncthreads();
    for (int off = 1; off < SCAN_T; off <<= 1) {
        int v = (t >= off) ? sp[t - off] : 0;
        __syncthreads();
        sp[t] += v;
        __syncthreads();
    }
    int base = (t == 0) ? 0 : sp[t - 1];
    for (int i = b0; i < b1; i++) {
        g_rowstart[i] = base;
        g_cursor[i]   = base;
        base += g_cnt[i];
    }
    if (t == SCAN_T - 1) g_rowstart[NNODES] = base;
}
__global__ void k_fill(const int* __restrict__ ei) {
    int e = blockIdx.x * blockDim.x + threadIdx.x;
    if (e >= ETOT) return;
    int s, d;
    if (e < E0) { s = ei[e]; d = ei[E0 + e]; }
    else        { s = e - E0; d = e - E0; }
    int pos = atomicAdd(&g_cursor[d], 1);
    g_col[pos] = s;
}

// ---------------------------------------------------------------------------
// Layer-1 transform: ft0 = x@W1 (x is 16-wide), logits as0/ad0.
// ---------------------------------------------------------------------------
__global__ void k_transform1(const float* __restrict__ xin,
                             const float* __restrict__ W,
                             const float* __restrict__ a_src,
                             const float* __restrict__ a_dst) {
    constexpr int IN = 16, D = 64, H = 8, C = 8, NPB = 16;
    __shared__ __align__(16) float sW[IN * D];
    __shared__ __align__(16) float sx[NPB][IN];
    __shared__ __align__(16) float sh[NPB][D];
    const int t  = threadIdx.x;
    const int li = t / 16;
    const int q  = t % 16;

    for (int i = t; i < IN * D / 4; i += 256)
        ((float4*)sW)[i] = ((const float4*)W)[i];

    const int ntiles = (NNODES + NPB - 1) / NPB;
    for (int tile = blockIdx.x; tile < ntiles; tile += gridDim.x) {
        __syncthreads();
        for (int i = t; i < NPB * IN; i += 256) {
            int nn = tile * NPB + i / IN;
            sx[i / IN][i % IN] = (nn < NNODES) ? xin[nn * IN + i % IN] : 0.f;
        }
        __syncthreads();
        const int n = tile * NPB + li;
        float4 acc = make_float4(0.f, 0.f, 0.f, 0.f);
#pragma unroll
        for (int i = 0; i < IN; i++) {
            float xv = sx[li][i];
            float4 w4 = *(const float4*)&sW[i * D + 4 * q];
            acc.x += xv * w4.x; acc.y += xv * w4.y;
            acc.z += xv * w4.z; acc.w += xv * w4.w;
        }
        if (n < NNODES) {
            *(float4*)&g_ft0[n * D + 4 * q] = acc;
            *(float4*)&sh[li][4 * q] = acc;
        }
        __syncthreads();
        if (t < NPB * H) {
            int ln = t / H, h = t % H;
            int nn = tile * NPB + ln;
            if (nn < NNODES) {
                float as = 0.f, ad = 0.f;
#pragma unroll
                for (int c = 0; c < C; c++) {
                    float hv = sh[ln][h * C + c];
                    as += hv * a_src[h * C + c];
                    ad += hv * a_dst[h * C + c];
                }
                g_as0[nn * H + h] = as;
                g_ad0[nn * H + h] = ad;
            }
        }
    }
}

// ---------------------------------------------------------------------------
// FUSED: aggregate current layer (H=8,C=8,D=64 softmax conv, +bias+ELU) and
// immediately transform the result by the NEXT layer's W + logits.
// One warp per dst node, grid-strided.  DOUT = 64 (layers 2,3) or 256 (layer4).
// FLIP selects ping-pong read buffers; writes go to the other side (or to the
// dedicated layer-4 buffers when DOUT==256).
// ---------------------------------------------------------------------------
template<int DOUT, bool FLIP>
__global__ void k_agg_fused(const float* __restrict__ bias,
                            const float* __restrict__ Wn,
                            const float* __restrict__ asn,
                            const float* __restrict__ adn) {
    extern __shared__ __align__(16) float smem[];
    float* sW = smem;                     // [64 * DOUT]
    float* sh = smem + 64 * DOUT;         // [8 warps][64]

    const float* __restrict__ ftin = FLIP ? g_ft1 : g_ft0;
    const float* __restrict__ asin_ = FLIP ? g_as1 : g_as0;
    const float* __restrict__ adin_ = FLIP ? g_ad1 : g_ad0;
    float* __restrict__ ftout = (DOUT == 256) ? g_ft4 : (FLIP ? g_ft0 : g_ft1);
    float* __restrict__ asout = (DOUT == 256) ? g_as4 : (FLIP ? g_as0 : g_as1);
    float* __restrict__ adout = (DOUT == 256) ? g_ad4 : (FLIP ? g_ad0 : g_ad1);

    const int t    = threadIdx.x;
    const int w    = t >> 5;
    const int lane = t & 31;

    // Stage next-layer W (64 x DOUT)
    for (int i = t; i < 64 * DOUT / 4; i += 256)
        ((float4*)sW)[i] = ((const float4*)Wn)[i];
    __syncthreads();

    const int nw = gridDim.x * 8;
    for (int d = blockIdx.x * 8 + w; d < NNODES; d += nw) {
        // ---- aggregate: channels (2*lane, 2*lane+1), head lane>>2 ----
        const int h  = lane >> 2;
        const float adv = adin_[d * 8 + h];
        const int r0 = g_rowstart[d];
        const int r1 = g_rowstart[d + 1];
        float den = 0.f, ax = 0.f, ay = 0.f;
#pragma unroll 4
        for (int j = r0; j < r1; j++) {
            int s = g_col[j];
            float e = __expf(leaky02(asin_[s * 8 + h] + adv));
            den += e;
            float2 f = *(const float2*)&ftin[s * 64 + 2 * lane];
            ax += e * f.x;
            ay += e * f.y;
        }
        float inv = 1.f / den;
        float ox = eluf(ax * inv + bias[2 * lane]);
        float oy = eluf(ay * inv + bias[2 * lane + 1]);
        sh[w * 64 + 2 * lane]     = ox;
        sh[w * 64 + 2 * lane + 1] = oy;
        __syncwarp();

        // ---- transform by next layer's W ----
        if (DOUT == 64) {
            float2 acc = make_float2(0.f, 0.f);
#pragma unroll
            for (int k = 0; k < 64; k++) {
                float xv = sh[w * 64 + k];
                float2 w2 = *(const float2*)&sW[k * 64 + 2 * lane];
                acc.x += xv * w2.x;
                acc.y += xv * w2.y;
            }
            *(float2*)&ftout[d * 64 + 2 * lane] = acc;
            // logits: head = (2*lane)/8 = lane>>2, flat a indexing by channel
            float pas = acc.x * asn[2 * lane] + acc.y * asn[2 * lane + 1];
            float pad = acc.x * adn[2 * lane] + acc.y * adn[2 * lane + 1];
            pas += __shfl_xor_sync(0xffffffff, pas, 1);
            pas += __shfl_xor_sync(0xffffffff, pas, 2);
            pad += __shfl_xor_sync(0xffffffff, pad, 1);
            pad += __shfl_xor_sync(0xffffffff, pad, 2);
            if ((lane & 3) == 0) {
                asout[d * 8 + (lane >> 2)] = pas;
                adout[d * 8 + (lane >> 2)] = pad;
            }
        } else {
            // lane owns channels [8*lane, 8*lane+8) of 256
            float4 a0 = make_float4(0.f, 0.f, 0.f, 0.f);
            float4 a1 = make_float4(0.f, 0.f, 0.f, 0.f);
#pragma unroll
            for (int k = 0; k < 64; k++) {
                float xv = sh[w * 64 + k];
                float4 wa = *(const float4*)&sW[k * 256 + 8 * lane];
                float4 wb = *(const float4*)&sW[k * 256 + 8 * lane + 4];
                a0.x += xv * wa.x; a0.y += xv * wa.y;
                a0.z += xv * wa.z; a0.w += xv * wa.w;
                a1.x += xv * wb.x; a1.y += xv * wb.y;
                a1.z += xv * wb.z; a1.w += xv * wb.w;
            }
            *(float4*)&ftout[d * 256 + 8 * lane]     = a0;
            *(float4*)&ftout[d * 256 + 8 * lane + 4] = a1;
            // logits: head = (8*lane)/64 = lane>>3
            const float* asc = &asn[8 * lane];
            const float* adc = &adn[8 * lane];
            float pas = a0.x * asc[0] + a0.y * asc[1] + a0.z * asc[2] + a0.w * asc[3]
                      + a1.x * asc[4] + a1.y * asc[5] + a1.z * asc[6] + a1.w * asc[7];
            float pad = a0.x * adc[0] + a0.y * adc[1] + a0.z * adc[2] + a0.w * adc[3]
                      + a1.x * adc[4] + a1.y * adc[5] + a1.z * adc[6] + a1.w * adc[7];
            pas += __shfl_xor_sync(0xffffffff, pas, 1);
            pas += __shfl_xor_sync(0xffffffff, pas, 2);
            pas += __shfl_xor_sync(0xffffffff, pas, 4);
            pad += __shfl_xor_sync(0xffffffff, pad, 1);
            pad += __shfl_xor_sync(0xffffffff, pad, 2);
            pad += __shfl_xor_sync(0xffffffff, pad, 4);
            if ((lane & 7) == 0) {
                asout[d * 4 + (lane >> 3)] = pas;
                adout[d * 4 + (lane >> 3)] = pad;
            }
        }
        __syncwarp();
    }
}

// ---------------------------------------------------------------------------
// Layer-4 aggregation (H=4, C=64, mean over heads) -> featA with bias+ELU.
// ---------------------------------------------------------------------------
__global__ void k_agg4(const float* __restrict__ bias) {
    int wid  = (blockIdx.x * blockDim.x + threadIdx.x) >> 5;
    int lane = threadIdx.x & 31;
    if (wid >= NNODES) return;
    const int d = wid;
    const float4 adv = *(const float4*)&g_ad4[d * 4];
    const int r0 = g_rowstart[d];
    const int r1 = g_rowstart[d + 1];

    float den[4] = {0.f, 0.f, 0.f, 0.f};
    float ax[4]  = {0.f, 0.f, 0.f, 0.f};
    float ay[4]  = {0.f, 0.f, 0.f, 0.f};
#pragma unroll 2
    for (int j = r0; j < r1; j++) {
        int s = g_col[j];
        float4 as4 = *(const float4*)&g_as4[s * 4];
        float ev[4];
        ev[0] = __expf(leaky02(as4.x + adv.x));
        ev[1] = __expf(leaky02(as4.y + adv.y));
        ev[2] = __expf(leaky02(as4.z + adv.z));
        ev[3] = __expf(leaky02(as4.w + adv.w));
#pragma unroll
        for (int hh = 0; hh < 4; hh++) {
            float2 f = *(const float2*)&g_ft4[s * 256 + hh * 64 + 2 * lane];
            den[hh] += ev[hh];
            ax[hh]  += ev[hh] * f.x;
            ay[hh]  += ev[hh] * f.y;
        }
    }
    float v1 = 0.f, v2 = 0.f;
#pragma unroll
    for (int hh = 0; hh < 4; hh++) {
        float inv = 1.f / den[hh];
        v1 += ax[hh] * inv;
        v2 += ay[hh] * inv;
    }
    float2 b = *(const float2*)&bias[2 * lane];
    float2 o;
    o.x = eluf(0.25f * v1 + b.x);
    o.y = eluf(0.25f * v2 + b.y);
    *(float2*)&g_featA[d * 64 + 2 * lane] = o;
}

// ---------------------------------------------------------------------------
// Pooling (flag sorted) + head
// ---------------------------------------------------------------------------
__global__ void k_zero_fp() {
    int t = threadIdx.x;
    if (t < NG * 64) g_fp[t] = 0.f;
}
__global__ void k_pool(const int* __restrict__ fidx, const int* __restrict__ flag, int nf) {
    int c   = threadIdx.x & 63;
    int row = threadIdx.x >> 6;
    int per = (nf + gridDim.x - 1) / gridDim.x;
    int i0  = blockIdx.x * per;
    int i1  = min(i0 + per, nf);
    float acc = 0.f;
    int cur = -1;
    for (int i = i0 + row; i < i1; i += 4) {
        int g = flag[i];
        float v = g_featA[fidx[i] * 64 + c];
        if (g != cur) {
            if (cur >= 0) atomicAdd(&g_fp[cur * 64 + c], acc);
            cur = g; acc = 0.f;
        }
        acc += v;
    }
    if (cur >= 0) atomicAdd(&g_fp[cur * 64 + c], acc);
}
__global__ void k_head(const int* __restrict__ dvi,
                       const float* __restrict__ Wp,
                       const float* __restrict__ Wt,
                       const float* __restrict__ Wo,
                       const float* __restrict__ bo,
                       float* __restrict__ out) {
    __shared__ float sfp[64], stg[64], red[128];
    int g = blockIdx.x, t = threadIdx.x;
    if (t < 64) {
        sfp[t] = g_fp[g * 64 + t];
        stg[t] = g_featA[dvi[g] * 64 + t];
    }
    __syncthreads();
    float acc = 0.f;
    if (t < 64) {
#pragma unroll
        for (int k = 0; k < 64; k++) acc += sfp[k] * Wp[k * 64 + t];
    } else {
        int c = t - 64;
#pragma unroll
        for (int k = 0; k < 64; k++) acc += stg[k] * Wt[k * 64 + c];
    }
    red[t] = eluf(acc) * Wo[t];
    __syncthreads();
    for (int s2 = 64; s2 > 0; s2 >>= 1) {
        if (t < s2) red[t] += red[t + s2];
        __syncthreads();
    }
    if (t == 0) out[g] = red[0] + bo[0];
}

// ---------------------------------------------------------------------------
extern "C" void kernel_launch(void* const* d_in, const int* in_sizes, int n_in,
                              void* d_out, int out_size) {
    const float* x     = (const float*)d_in[0];
    const int*   ei    = (const int*)  d_in[1];
    const int*   fidx  = (const int*)  d_in[2];
    const int*   flag  = (const int*)  d_in[3];
    const int*   dvi   = (const int*)  d_in[4];
    const float* W1    = (const float*)d_in[5];
    const float* as1   = (const float*)d_in[6];
    const float* ad1   = (const float*)d_in[7];
    const float* b1    = (const float*)d_in[8];
    const float* W2    = (const float*)d_in[9];
    const float* as2   = (const float*)d_in[10];
    const float* ad2   = (const float*)d_in[11];
    const float* b2    = (const float*)d_in[12];
    const float* W3    = (const float*)d_in[13];
    const float* as3   = (const float*)d_in[14];
    const float* ad3   = (const float*)d_in[15];
    const float* b3    = (const float*)d_in[16];
    const float* W4    = (const float*)d_in[17];
    const float* as4   = (const float*)d_in[18];
    const float* ad4   = (const float*)d_in[19];
    const float* b4    = (const float*)d_in[20];
    const float* Wp    = (const float*)d_in[21];
    const float* Wt    = (const float*)d_in[22];
    const float* Wo    = (const float*)d_in[23];
    const float* bo    = (const float*)d_in[24];
    float* out = (float*)d_out;

    const int nf = in_sizes[2];                // 8000
    const int EB = (ETOT + 255) / 256;
    const int NB = (NNODES + 255) / 256;
    const int AB = (NNODES * 32 + 255) / 256;  // warp-per-node

    const int SM64  = (64 * 64 + 8 * 64) * 4;   // 18432 B
    const int SM256 = (64 * 256 + 8 * 64) * 4;  // 67584 B
    static bool attr_done = false;
    if (!attr_done) {
        cudaFuncSetAttribute(k_agg_fused<256, false>,
                             cudaFuncAttributeMaxDynamicSharedMemorySize, SM256);
        attr_done = true;
    }

    // ---- CSR build ----
    k_zero_cnt<<<NB, 256>>>();
    k_count<<<EB, 256>>>(ei);
    k_scan<<<1, SCAN_T>>>();
    k_fill<<<EB, 256>>>(ei);

    // ---- Layer 1 transform ----
    k_transform1<<<625, 256>>>(x, W1, as1, ad1);
    // ---- agg L1 + transform L2 (ft0 -> ft1) ----
    k_agg_fused<64, false><<<592, 256, SM64>>>(b1, W2, as2, ad2);
    // ---- agg L2 + transform L3 (ft1 -> ft0) ----
    k_agg_fused<64, true><<<592, 256, SM64>>>(b2, W3, as3, ad3);
    // ---- agg L3 + transform L4 (ft0 -> ft4) ----
    k_agg_fused<256, false><<<444, 256, SM256>>>(b3, W4, as4, ad4);
    // ---- agg L4 -> featA ----
    k_agg4<<<AB, 256>>>(b4);

    // ---- Pool + head ----
    k_zero_fp<<<1, 512>>>();
    k_pool<<<32, 256>>>(fidx, flag, nf);
    k_head<<<NG, 128>>>(dvi, Wp, Wt, Wo, bo, out);
}

// round 6
// speedup vs baseline: 1.0555x; 1.0555x over previous
#include <cuda_runtime.h>
#include <cuda_fp16.h>
#include <math.h>

// ---------------------------------------------------------------------------
// GATNet: 4x GATConv + pool + MLP head.  CSR-by-dst, single-pass softmax
// (no max subtraction), fp16 feature gathers (fp32 accumulate), tiled
// transforms.  Unfused (R3 structure -- fusion lost occupancy in R4).
// ---------------------------------------------------------------------------

#define NNODES 20000
#define E0     320000
#define ETOT   (E0 + NNODES)
#define NG     8
#define SCAN_T 1024
#define SCAN_CHUNK ((NNODES + SCAN_T - 1) / SCAN_T)   // 20

// Scratch (device globals; no allocations allowed)
__device__ __align__(16) float  g_featA[NNODES * 64];   // layer input (post-ELU), fp32
__device__ __align__(16) __half g_featT[NNODES * 64];   // transformed feats, fp16 (L1-3)
__device__ __align__(16) __half g_ft4  [NNODES * 256];  // transformed feats, fp16 (L4)
__device__ __align__(16) float  g_asrc [NNODES * 8];
__device__ __align__(16) float  g_adst [NNODES * 8];
__device__ float g_fp[NG * 64];
// CSR by destination.  g_cnt is zero on entry to every call: statically
// zero-initialized for call #1, and re-zeroed by k_fill each call.
__device__ int g_cnt[NNODES];
__device__ int g_rowstart[NNODES + 1];
__device__ int g_cursor[NNODES];
__device__ int g_col[ETOT];

__device__ __forceinline__ float leaky02(float v) { return fmaxf(v, 0.2f * v); }
__device__ __forceinline__ float eluf(float v)    { return v > 0.f ? v : (__expf(v) - 1.f); }

// ---------------------------------------------------------------------------
// CSR build
// ---------------------------------------------------------------------------
__global__ void k_count(const int* __restrict__ ei) {
    int e = blockIdx.x * blockDim.x + threadIdx.x;
    if (e >= ETOT) return;
    int d = (e < E0) ? ei[E0 + e] : (e - E0);
    atomicAdd(&g_cnt[d], 1);
}
__global__ void k_scan() {
    __shared__ int sp[SCAN_T];
    int t = threadIdx.x;
    if (t < NG * 64) g_fp[t] = 0.f;          // piggyback: zero pool accumulator
    int b0 = t * SCAN_CHUNK;
    int b1 = min(b0 + SCAN_CHUNK, NNODES);
    int sum = 0;
    for (int i = b0; i < b1; i++) sum += g_cnt[i];
    sp[t] = sum;
    __syncthreads();
    for (int off = 1; off < SCAN_T; off <<= 1) {
        int v = (t >= off) ? sp[t - off] : 0;
        __syncthreads();
        sp[t] += v;
        __syncthreads();
    }
    int base = (t == 0) ? 0 : sp[t - 1];
    for (int i = b0; i < b1; i++) {
        g_rowstart[i] = base;
        g_cursor[i]   = base;
        base += g_cnt[i];
    }
    if (t == SCAN_T - 1) g_rowstart[NNODES] = base;
}
__global__ void k_fill(const int* __restrict__ ei) {
    int e = blockIdx.x * blockDim.x + threadIdx.x;
    if (e < NNODES) g_cnt[e] = 0;            // self-clean for next call
    if (e >= ETOT) return;
    int s, d;
    if (e < E0) { s = ei[e]; d = ei[E0 + e]; }
    else        { s = e - E0; d = e - E0; }
    int pos = atomicAdd(&g_cursor[d], 1);
    g_col[pos] = s;
}

// ---------------------------------------------------------------------------
// Tiled node transform: featT(half) = x@W, logits asrc/adst (fp32).
// Thread = (node-in-tile, out-quad).  W staged in shared when STAGE_W.
// D64 writes g_featT, D256 writes g_ft4.
// ---------------------------------------------------------------------------
template<int IN, int D, int H, int C, bool USE_G, bool STAGE_W>
__global__ void k_transform(const float* __restrict__ xin,
                            const float* __restrict__ W,
                            const float* __restrict__ a_src,
                            const float* __restrict__ a_dst) {
    constexpr int QUADS = D / 4;
    constexpr int NPB   = 256 / QUADS;          // 16 (D=64) or 4 (D=256)
    __shared__ __align__(16) float sW[STAGE_W ? IN * D : 4];
    __shared__ __align__(16) float sx[NPB][IN];
    __shared__ __align__(16) float sh[NPB][D];

    const int t  = threadIdx.x;
    const int li = t / QUADS;
    const int q  = t % QUADS;
    const float* __restrict__ xp = USE_G ? (const float*)g_featA : xin;
    __half* __restrict__ fout = (D == 256) ? g_ft4 : g_featT;

    if (STAGE_W) {
        for (int i = t; i < IN * D / 4; i += 256)
            ((float4*)sW)[i] = ((const float4*)W)[i];
    }

    const int ntiles = (NNODES + NPB - 1) / NPB;
    for (int tile = blockIdx.x; tile < ntiles; tile += gridDim.x) {
        __syncthreads();
        for (int i = t; i < NPB * IN; i += 256) {
            int nn = tile * NPB + i / IN;
            sx[i / IN][i % IN] = (nn < NNODES) ? xp[nn * IN + i % IN] : 0.f;
        }
        __syncthreads();

        const int n = tile * NPB + li;
        float4 acc = make_float4(0.f, 0.f, 0.f, 0.f);
#pragma unroll
        for (int i = 0; i < IN; i++) {
            float xv = sx[li][i];
            float4 w4 = STAGE_W ? *(const float4*)&sW[i * D + 4 * q]
                                : __ldg((const float4*)&W[i * D + 4 * q]);
            acc.x += xv * w4.x; acc.y += xv * w4.y;
            acc.z += xv * w4.z; acc.w += xv * w4.w;
        }
        if (n < NNODES) {
            __half2* dst = (__half2*)&fout[n * D + 4 * q];
            dst[0] = __floats2half2_rn(acc.x, acc.y);
            dst[1] = __floats2half2_rn(acc.z, acc.w);
            *(float4*)&sh[li][4 * q] = acc;
        }
        __syncthreads();

        if (t < NPB * H) {
            int ln = t / H, h = t % H;
            int nn = tile * NPB + ln;
            if (nn < NNODES) {
                float as = 0.f, ad = 0.f;
#pragma unroll
                for (int c = 0; c < C; c++) {
                    float hv = sh[ln][h * C + c];
                    as += hv * a_src[h * C + c];
                    ad += hv * a_dst[h * C + c];
                }
                g_asrc[nn * H + h] = as;
                g_adst[nn * H + h] = ad;
            }
        }
    }
}

// ---------------------------------------------------------------------------
// Fused aggregation, concat layers (H=8, C=8, D=64).  One warp per dst node.
// Lane L owns channel pair (2L, 2L+1) -> head L>>2.  fp16 feature gathers.
// ---------------------------------------------------------------------------
__global__ void k_agg8(const float* __restrict__ bias) {
    int wid  = (blockIdx.x * blockDim.x + threadIdx.x) >> 5;
    int lane = threadIdx.x & 31;
    if (wid >= NNODES) return;
    const int d = wid;
    const int h = lane >> 2;
    const float adv = g_adst[d * 8 + h];
    const int r0 = g_rowstart[d];
    const int r1 = g_rowstart[d + 1];
    const __half2* __restrict__ ft = (const __half2*)g_featT;

    float den = 0.f, ax = 0.f, ay = 0.f;
#pragma unroll 8
    for (int j = r0; j < r1; j++) {
        int s = g_col[j];
        float e = __expf(leaky02(g_asrc[s * 8 + h] + adv));
        den += e;
        float2 f = __half22float2(ft[s * 32 + lane]);
        ax += e * f.x;
        ay += e * f.y;
    }
    float inv = 1.f / den;
    float2 b = *(const float2*)&bias[2 * lane];
    float2 o;
    o.x = eluf(ax * inv + b.x);
    o.y = eluf(ay * inv + b.y);
    *(float2*)&g_featA[d * 64 + 2 * lane] = o;
}

// ---------------------------------------------------------------------------
// Fused aggregation, layer 4 (H=4, C=64, mean over heads).  Warp per node,
// lane L owns channel pair (2L, 2L+1), loops all 4 heads.  fp16 gathers.
// ---------------------------------------------------------------------------
__global__ void k_agg4(const float* __restrict__ bias) {
    int wid  = (blockIdx.x * blockDim.x + threadIdx.x) >> 5;
    int lane = threadIdx.x & 31;
    if (wid >= NNODES) return;
    const int d = wid;
    const float4 adv = *(const float4*)&g_adst[d * 4];
    const int r0 = g_rowstart[d];
    const int r1 = g_rowstart[d + 1];
    const __half2* __restrict__ ft = (const __half2*)g_ft4;

    float den[4] = {0.f, 0.f, 0.f, 0.f};
    float ax[4]  = {0.f, 0.f, 0.f, 0.f};
    float ay[4]  = {0.f, 0.f, 0.f, 0.f};
#pragma unroll 4
    for (int j = r0; j < r1; j++) {
        int s = g_col[j];
        float4 as4 = *(const float4*)&g_asrc[s * 4];
        float ev[4];
        ev[0] = __expf(leaky02(as4.x + adv.x));
        ev[1] = __expf(leaky02(as4.y + adv.y));
        ev[2] = __expf(leaky02(as4.z + adv.z));
        ev[3] = __expf(leaky02(as4.w + adv.w));
#pragma unroll
        for (int hh = 0; hh < 4; hh++) {
            float2 f = __half22float2(ft[s * 128 + hh * 32 + lane]);
            den[hh] += ev[hh];
            ax[hh]  += ev[hh] * f.x;
            ay[hh]  += ev[hh] * f.y;
        }
    }
    float v1 = 0.f, v2 = 0.f;
#pragma unroll
    for (int hh = 0; hh < 4; hh++) {
        float inv = 1.f / den[hh];
        v1 += ax[hh] * inv;
        v2 += ay[hh] * inv;
    }
    float2 b = *(const float2*)&bias[2 * lane];
    float2 o;
    o.x = eluf(0.25f * v1 + b.x);
    o.y = eluf(0.25f * v2 + b.y);
    *(float2*)&g_featA[d * 64 + 2 * lane] = o;
}

// ---------------------------------------------------------------------------
// Pooling (flag sorted): register run-accumulation, few atomics.
// ---------------------------------------------------------------------------
__global__ void k_pool(const int* __restrict__ fidx, const int* __restrict__ flag, int nf) {
    int c   = threadIdx.x & 63;
    int row = threadIdx.x >> 6;
    int per = (nf + gridDim.x - 1) / gridDim.x;
    int i0  = blockIdx.x * per;
    int i1  = min(i0 + per, nf);
    float acc = 0.f;
    int cur = -1;
    for (int i = i0 + row; i < i1; i += 4) {
        int g = flag[i];
        float v = g_featA[fidx[i] * 64 + c];
        if (g != cur) {
            if (cur >= 0) atomicAdd(&g_fp[cur * 64 + c], acc);
            cur = g; acc = 0.f;
        }
        acc += v;
    }
    if (cur >= 0) atomicAdd(&g_fp[cur * 64 + c], acc);
}

// ---------------------------------------------------------------------------
// Head: z = elu([fp@Wp, h4[dvi]@Wt]); out = z@Wo + bo
// ---------------------------------------------------------------------------
__global__ void k_head(const int* __restrict__ dvi,
                       const float* __restrict__ Wp,
                       const float* __restrict__ Wt,
                       const float* __restrict__ Wo,
                       const float* __restrict__ bo,
                       float* __restrict__ out) {
    __shared__ float sfp[64], stg[64], red[128];
    int g = blockIdx.x, t = threadIdx.x;
    if (t < 64) {
        sfp[t] = g_fp[g * 64 + t];
        stg[t] = g_featA[dvi[g] * 64 + t];
    }
    __syncthreads();
    float acc = 0.f;
    if (t < 64) {
#pragma unroll
        for (int k = 0; k < 64; k++) acc += sfp[k] * Wp[k * 64 + t];
    } else {
        int c = t - 64;
#pragma unroll
        for (int k = 0; k < 64; k++) acc += stg[k] * Wt[k * 64 + c];
    }
    red[t] = eluf(acc) * Wo[t];
    __syncthreads();
    for (int s2 = 64; s2 > 0; s2 >>= 1) {
        if (t < s2) red[t] += red[t + s2];
        __syncthreads();
    }
    if (t == 0) out[g] = red[0] + bo[0];
}

// ---------------------------------------------------------------------------
extern "C" void kernel_launch(void* const* d_in, const int* in_sizes, int n_in,
                              void* d_out, int out_size) {
    const float* x     = (const float*)d_in[0];
    const int*   ei    = (const int*)  d_in[1];
    const int*   fidx  = (const int*)  d_in[2];
    const int*   flag  = (const int*)  d_in[3];
    const int*   dvi   = (const int*)  d_in[4];
    const float* W1    = (const float*)d_in[5];
    const float* as1   = (const float*)d_in[6];
    const float* ad1   = (const float*)d_in[7];
    const float* b1    = (const float*)d_in[8];
    const float* W2    = (const float*)d_in[9];
    const float* as2   = (const float*)d_in[10];
    const float* ad2   = (const float*)d_in[11];
    const float* b2    = (const float*)d_in[12];
    const float* W3    = (const float*)d_in[13];
    const float* as3   = (const float*)d_in[14];
    const float* ad3   = (const float*)d_in[15];
    const float* b3    = (const float*)d_in[16];
    const float* W4    = (const float*)d_in[17];
    const float* as4   = (const float*)d_in[18];
    const float* ad4   = (const float*)d_in[19];
    const float* b4    = (const float*)d_in[20];
    const float* Wp    = (const float*)d_in[21];
    const float* Wt    = (const float*)d_in[22];
    const float* Wo    = (const float*)d_in[23];
    const float* bo    = (const float*)d_in[24];
    float* out = (float*)d_out;

    const int nf = in_sizes[2];                // 8000
    const int EB = (ETOT + 255) / 256;
    const int AB = (NNODES * 32 + 255) / 256;  // warp-per-node

    // ---- CSR build (g_cnt zero on entry; k_fill re-zeros it) ----
    k_count<<<EB, 256>>>(ei);
    k_scan<<<1, SCAN_T>>>();
    k_fill<<<EB, 256>>>(ei);

    // ---- Layer 1: 16 -> 8x8 concat ----
    k_transform<16, 64, 8, 8, false, true><<<625, 256>>>(x, W1, as1, ad1);
    k_agg8<<<AB, 256>>>(b1);
    // ---- Layer 2 ----
    k_transform<64, 64, 8, 8, true, true><<<625, 256>>>(nullptr, W2, as2, ad2);
    k_agg8<<<AB, 256>>>(b2);
    // ---- Layer 3 ----
    k_transform<64, 64, 8, 8, true, true><<<625, 256>>>(nullptr, W3, as3, ad3);
    k_agg8<<<AB, 256>>>(b3);
    // ---- Layer 4: 64 -> 4 heads x 64, mean ----
    k_transform<64, 256, 4, 64, true, false><<<2500, 256>>>(nullptr, W4, as4, ad4);
    k_agg4<<<AB, 256>>>(b4);

    // ---- Pool + head ----
    k_pool<<<32, 256>>>(fidx, flag, nf);
    k_head<<<NG, 128>>>(dvi, Wp, Wt, Wo, bo, out);
}